// round 17
// baseline (speedup 1.0000x reference)
#include <cuda_runtime.h>
#include <math.h>
#include <stdint.h>

// GRU: B=32, S=2048, H=512, 2 layers. fp32 (f32x2-packed math).
#define H   512
#define Bz  32
#define Sz  2048
#define G3  1536

// ---------------- static device scratch (no allocations allowed) -------------
__device__ float g_ip[(size_t)Sz * Bz * G3];   // input-projection buffer
__device__ float g_y0[(size_t)Sz * Bz * H];    // layer0 output, [s][b][h]
__device__ float g_h[2][Bz * H];               // double-buffered hidden state
__device__ unsigned long long g_cnt8[8][16];   // per-group barrier arrivals
__device__ unsigned long long g_gen8[8][16];   // per-group barrier generation

// ---------------- packed f32x2 helpers (Blackwell) ---------------------------
#define FMA2(d, a, b, c) \
    asm("fma.rn.f32x2 %0, %1, %2, %3;" : "=l"(d) : "l"(a), "l"(b), "l"(c))

__device__ __forceinline__ unsigned long long pack2(float lo, float hi) {
    unsigned long long r;
    asm("mov.b64 %0, {%1, %2};" : "=l"(r) : "f"(lo), "f"(hi));
    return r;
}
__device__ __forceinline__ float2 unpack2(unsigned long long v) {
    float2 f;
    asm("mov.b64 {%0, %1}, %2;" : "=f"(f.x), "=f"(f.y) : "l"(v));
    return f;
}

// ---------------- release/acquire barrier primitives -------------------------
__device__ __forceinline__ unsigned long long atom_add_release(unsigned long long* p) {
    unsigned long long old;
    asm volatile("atom.release.gpu.global.add.u64 %0, [%1], 1;"
                 : "=l"(old) : "l"(p) : "memory");
    return old;
}
__device__ __forceinline__ void red_add_release(unsigned long long* p) {
    asm volatile("red.release.gpu.global.add.u64 [%0], 1;" :: "l"(p) : "memory");
}
__device__ __forceinline__ unsigned long long ld_acquire(unsigned long long* p) {
    unsigned long long v;
    asm volatile("ld.acquire.gpu.global.u64 %0, [%1];" : "=l"(v) : "l"(p) : "memory");
    return v;
}

// ---------------- persistent scan kernel config ------------------------------
// 128 blocks = 16 j-tiles (JT=32) x 8 batch-groups (BT=4). Barrier fan-in 16.
// Weights per CTA: 96 rows = 48 in registers + 48 in dynamic smem.
#define NBLK 128
#define NTHR 256           // 8 warps
#define JT   32            // j's per block
#define BT   4             // batches per block
#define ROWS 96            // 3 gates * JT
#define GRPBLK 16          // blocks per barrier group (same batch-group)
// dyn smem: w_s[48][512] + h_s[4][512] + hp_s[96][4]
#define SMEM_FLOATS (48 * H + BT * H + ROWS * BT)
#define SMEM_BYTES  (SMEM_FLOATS * 4)   // 108032 B

// Barrier over the 16 blocks sharing one batch-group (CG grid.sync pattern).
// Monotonic counters keep graph replays correct. Owner = last warp.
__device__ __forceinline__ void group_barrier(int grp)
{
    __syncthreads();
    if (threadIdx.x == NTHR - 1) {
        unsigned long long old = atom_add_release(&g_cnt8[grp][0]);
        unsigned long long epoch = old >> 4;              // /GRPBLK
        if ((old & (GRPBLK - 1)) == GRPBLK - 1) {
            red_add_release(&g_gen8[grp][0]);             // release all
        } else {
            while (ld_acquire(&g_gen8[grp][0]) <= epoch) { }
        }
    }
    __syncthreads();
}

__global__ __launch_bounds__(NTHR, 1)
void gru_scan_kernel(const float* __restrict__ ip,   // [S][B][3H] (bi included)
                     const float* __restrict__ Wh,   // [3H][H]
                     const float* __restrict__ bh,   // [3H]
                     float* __restrict__ y,          // l0: [s][b][h]; l1: [b][s][h]
                     float* __restrict__ hout,       // last hidden (layer1 only)
                     int last_layer)
{
    extern __shared__ float sm[];
    float* w_s  = sm;                        // [48][512] smem weight rows
    float* h_s  = sm + 48 * H;               // [4][512]  full h for 4 batches
    float* hp_s = h_s + BT * H;              // [96][4]

    const int tid  = threadIdx.x;
    const int w    = tid >> 5;               // warp 0..7
    const int lane = tid & 31;
    const int bid  = blockIdx.x;
    const int jt   = bid >> 3;               // 0..15
    const int bg   = bid & 7;                // 0..7 (barrier group)
    const int j0   = jt * JT;
    const int b0   = bg * BT;

    // ---- weights: warp w owns local rows [w*12, w*12+12); first 6 -> regs,
    //      last 6 -> smem (compact row id w*6+rr). r_loc = gate*32 + jl.
    unsigned long long wreg[6][8];
    #pragma unroll
    for (int rr = 0; rr < 6; rr++) {
        int r_loc = w * 12 + rr;
        int grow  = (r_loc >> 5) * H + j0 + (r_loc & 31);
        const unsigned long long* src =
            (const unsigned long long*)(Wh + (size_t)grow * H);
        #pragma unroll
        for (int i = 0; i < 8; i++)
            wreg[rr][i] = __ldg(src + lane + 32 * i);
    }
    {
        unsigned long long* ws2 = (unsigned long long*)w_s;
        #pragma unroll
        for (int rr = 0; rr < 6; rr++) {
            int r_loc = w * 12 + 6 + rr;
            int grow  = (r_loc >> 5) * H + j0 + (r_loc & 31);
            int srow  = w * 6 + rr;
            const unsigned long long* src =
                (const unsigned long long*)(Wh + (size_t)grow * H);
            #pragma unroll
            for (int i = 0; i < 8; i++)
                ws2[srow * (H / 2) + lane + 32 * i] = __ldg(src + lane + 32 * i);
        }
    }

    // ---- gate-thread constants (tid<128: one (j,b) output each) -------------
    float bhr = 0.f, bhz = 0.f, bhn = 0.f;
    int g_jl = 0, g_bb = 0, bglob = 0, gj = 0;
    const float* ipp = ip;
    const bool gthread = (tid < JT * BT);
    if (gthread) {
        g_jl  = tid >> 2;                // 0..31
        g_bb  = tid & 3;                 // 0..3
        bglob = b0 + g_bb;
        gj    = j0 + g_jl;
        bhr = __ldg(bh + gj); bhz = __ldg(bh + H + gj); bhn = __ldg(bh + 2 * H + gj);
        ipp = ip + (size_t)bglob * G3 + gj;
    }
    float ipr = 0.f, ipz = 0.f, ipn = 0.f;
    if (gthread) {                       // prefetch ip for t=0
        ipr = __ldg(ipp);
        ipz = __ldg(ipp + H);
        ipn = __ldg(ipp + 2 * H);
    }

    const unsigned long long* h2   = (const unsigned long long*)h_s;
    const unsigned long long* ws2c = (const unsigned long long*)w_s;

    for (int t = 0; t < Sz; t++) {
        // ---- stage current hidden slice (4 batches x 512) into smem ---------
        {
            const float4* hsrc = (const float4*)(&g_h[t & 1][b0 * H]);
            float4* hdst = (float4*)h_s;
            #pragma unroll
            for (int i = 0; i < (BT * H / 4) / NTHR; i++) {   // 2 iters
                int idx = tid + i * NTHR;
                float4 v;
                if (t == 0) v = make_float4(0.f, 0.f, 0.f, 0.f);
                else        v = __ldcg(hsrc + idx);           // bypass stale L1
                hdst[idx] = v;
            }
        }
        __syncthreads();

        // ---- hp = Wh_tile @ h : warp = 12 rows (6 reg + 6 smem) x 4 batches -
        unsigned long long accR[6][4], accS[6][4];
        #pragma unroll
        for (int rr = 0; rr < 6; rr++)
            #pragma unroll
            for (int b = 0; b < 4; b++) { accR[rr][b] = 0ULL; accS[rr][b] = 0ULL; }

        #pragma unroll
        for (int i = 0; i < 8; i++) {                         // k-pair chunks
            int p = lane + 32 * i;
            unsigned long long hv[4];
            #pragma unroll
            for (int b = 0; b < 4; b++) hv[b] = h2[b * (H / 2) + p];
            #pragma unroll
            for (int rr = 0; rr < 6; rr++) {
                #pragma unroll
                for (int b = 0; b < 4; b++)
                    FMA2(accR[rr][b], wreg[rr][i], hv[b], accR[rr][b]);
            }
            #pragma unroll
            for (int rr = 0; rr < 6; rr++) {
                unsigned long long wv = ws2c[(w * 6 + rr) * (H / 2) + p];
                #pragma unroll
                for (int b = 0; b < 4; b++)
                    FMA2(accS[rr][b], wv, hv[b], accS[rr][b]);
            }
        }
        #pragma unroll
        for (int rr = 0; rr < 6; rr++)
            #pragma unroll
            for (int b = 0; b < 4; b++) {
                float2 f = unpack2(accR[rr][b]);
                float v = f.x + f.y;
                v += __shfl_xor_sync(0xffffffffu, v, 16);
                v += __shfl_xor_sync(0xffffffffu, v, 8);
                v += __shfl_xor_sync(0xffffffffu, v, 4);
                v += __shfl_xor_sync(0xffffffffu, v, 2);
                v += __shfl_xor_sync(0xffffffffu, v, 1);
                if (lane == 0) hp_s[(w * 12 + rr) * BT + b] = v;
            }
        #pragma unroll
        for (int rr = 0; rr < 6; rr++)
            #pragma unroll
            for (int b = 0; b < 4; b++) {
                float2 f = unpack2(accS[rr][b]);
                float v = f.x + f.y;
                v += __shfl_xor_sync(0xffffffffu, v, 16);
                v += __shfl_xor_sync(0xffffffffu, v, 8);
                v += __shfl_xor_sync(0xffffffffu, v, 4);
                v += __shfl_xor_sync(0xffffffffu, v, 2);
                v += __shfl_xor_sync(0xffffffffu, v, 1);
                if (lane == 0) hp_s[(w * 12 + 6 + rr) * BT + b] = v;
            }
        __syncthreads();

        // ---- gates + state update ------------------------------------------
        if (gthread) {
            float hpr = hp_s[(g_jl) * BT + g_bb] + bhr;           // gate r rows 0..31
            float hpz = hp_s[(JT + g_jl) * BT + g_bb] + bhz;      // gate z rows 32..63
            float hpn = hp_s[(2 * JT + g_jl) * BT + g_bb] + bhn;  // gate n rows 64..95
            float hprev = h_s[g_bb * H + gj];
            float r = 1.f / (1.f + __expf(-(ipr + hpr)));
            float z = 1.f / (1.f + __expf(-(ipz + hpz)));
            float n = tanhf(ipn + r * hpn);
            float hy = (1.f - z) * n + z * hprev;
            __stcg(&g_h[(t + 1) & 1][bglob * H + gj], hy);
            if (last_layer) {
                y[((size_t)bglob * Sz + t) * H + gj] = hy;
                if (t == Sz - 1) hout[bglob * H + gj] = hy;
            } else {
                y[((size_t)t * Bz + bglob) * H + gj] = hy;
            }
            // prefetch next step's ip (DRAM latency hides under the barrier)
            if (t != Sz - 1) {
                const float* p = ipp + (size_t)(t + 1) * (Bz * G3);
                ipr = __ldg(p);
                ipz = __ldg(p + H);
                ipn = __ldg(p + 2 * H);
            }
        }
        if (t != Sz - 1) group_barrier(bg);
    }
}

// ---------------- fp32 input-projection GEMM (f32x2 + double-buffered) -------
// C[m][g] = sum_d A[row(m)][d] * W[g][d] + bias[g];  M=65536, N=1536, K=512
// row(m) offset = (m&31)*strideB + (m>>5)*strideS
#define GBM 128
#define GBN 128
#define GBK 8

__global__ __launch_bounds__(256, 1)
void gemm_wi_kernel(const float* __restrict__ A, const float* __restrict__ W,
                    const float* __restrict__ bias, float* __restrict__ C,
                    int strideB, int strideS)
{
    __shared__ __align__(16) float As[2][GBK][GBM];
    __shared__ __align__(16) float Bs[2][GBK][GBN];

    const int tid = threadIdx.x;
    const int m0 = blockIdx.y * GBM;
    const int n0 = blockIdx.x * GBN;
    const int ty = tid >> 4, tx = tid & 15;

    const int lrow = tid >> 1;
    const int lk   = (tid & 1) * 4;

    const int am = m0 + lrow;
    const size_t aoff = (size_t)(am & 31) * strideB + (size_t)(am >> 5) * strideS;
    const size_t boff = (size_t)(n0 + lrow) * H;

    unsigned long long acc2[8][4];
    #pragma unroll
    for (int i = 0; i < 8; i++)
        #pragma unroll
        for (int j = 0; j < 4; j++) acc2[i][j] = 0ULL;

    {
        float4 av = *(const float4*)(A + aoff + lk);
        float4 bv = *(const float4*)(W + boff + lk);
        As[0][lk + 0][lrow] = av.x; As[0][lk + 1][lrow] = av.y;
        As[0][lk + 2][lrow] = av.z; As[0][lk + 3][lrow] = av.w;
        Bs[0][lk + 0][lrow] = bv.x; Bs[0][lk + 1][lrow] = bv.y;
        Bs[0][lk + 2][lrow] = bv.z; Bs[0][lk + 3][lrow] = bv.w;
    }
    __syncthreads();

    int buf = 0;
    for (int k0 = 0; k0 < H; k0 += GBK) {
        float4 av, bv;
        const bool more = (k0 + GBK < H);
        if (more) {
            av = *(const float4*)(A + aoff + k0 + GBK + lk);
            bv = *(const float4*)(W + boff + k0 + GBK + lk);
        }

        #pragma unroll
        for (int k = 0; k < GBK; k++) {
            float4 a0 = *(float4*)&As[buf][k][ty * 8];
            float4 a1 = *(float4*)&As[buf][k][ty * 8 + 4];
            float4 b0 = *(float4*)&Bs[buf][k][tx * 8];
            float4 b1 = *(float4*)&Bs[buf][k][tx * 8 + 4];
            unsigned long long a2[8];
            a2[0] = pack2(a0.x, a0.x); a2[1] = pack2(a0.y, a0.y);
            a2[2] = pack2(a0.z, a0.z); a2[3] = pack2(a0.w, a0.w);
            a2[4] = pack2(a1.x, a1.x); a2[5] = pack2(a1.y, a1.y);
            a2[6] = pack2(a1.z, a1.z); a2[7] = pack2(a1.w, a1.w);
            unsigned long long b2[4];
            b2[0] = pack2(b0.x, b0.y); b2[1] = pack2(b0.z, b0.w);
            b2[2] = pack2(b1.x, b1.y); b2[3] = pack2(b1.z, b1.w);
            #pragma unroll
            for (int i = 0; i < 8; i++)
                #pragma unroll
                for (int j = 0; j < 4; j++)
                    FMA2(acc2[i][j], a2[i], b2[j], acc2[i][j]);
        }

        if (more) {
            int nb = buf ^ 1;
            As[nb][lk + 0][lrow] = av.x; As[nb][lk + 1][lrow] = av.y;
            As[nb][lk + 2][lrow] = av.z; As[nb][lk + 3][lrow] = av.w;
            Bs[nb][lk + 0][lrow] = bv.x; Bs[nb][lk + 1][lrow] = bv.y;
            Bs[nb][lk + 2][lrow] = bv.z; Bs[nb][lk + 3][lrow] = bv.w;
            __syncthreads();
            buf = nb;
        }
    }

    float bia[8];
    #pragma unroll
    for (int j = 0; j < 8; j++) bia[j] = __ldg(bias + n0 + tx * 8 + j);

    #pragma unroll
    for (int i = 0; i < 8; i++) {
        int m = m0 + ty * 8 + i;
        float* crow = C + (size_t)m * G3 + n0 + tx * 8;
        float2 p0 = unpack2(acc2[i][0]);
        float2 p1 = unpack2(acc2[i][1]);
        float2 p2 = unpack2(acc2[i][2]);
        float2 p3 = unpack2(acc2[i][3]);
        float4 o0 = make_float4(p0.x + bia[0], p0.y + bia[1],
                                p1.x + bia[2], p1.y + bia[3]);
        float4 o1 = make_float4(p2.x + bia[4], p2.y + bia[5],
                                p3.x + bia[6], p3.y + bia[7]);
        *(float4*)(crow)     = o0;
        *(float4*)(crow + 4) = o1;
    }
}

// ---------------- launch ------------------------------------------------------
extern "C" void kernel_launch(void* const* d_in, const int* in_sizes, int n_in,
                              void* d_out, int out_size)
{
    const float* x   = (const float*)d_in[0];
    const float* Wi0 = (const float*)d_in[1];
    const float* bi0 = (const float*)d_in[2];
    const float* Wh0 = (const float*)d_in[3];
    const float* bh0 = (const float*)d_in[4];
    const float* Wi1 = (const float*)d_in[5];
    const float* bi1 = (const float*)d_in[6];
    const float* Wh1 = (const float*)d_in[7];
    const float* bh1 = (const float*)d_in[8];
    float* out = (float*)d_out;

    float *ip, *y0;
    cudaGetSymbolAddress((void**)&ip, g_ip);
    cudaGetSymbolAddress((void**)&y0, g_y0);

    cudaFuncSetAttribute(gru_scan_kernel,
                         cudaFuncAttributeMaxDynamicSharedMemorySize, SMEM_BYTES);

    dim3 gg(G3 / GBN, (Bz * Sz) / GBM);   // 12 x 512

    // layer 0: ip = x @ Wi0^T + bi0, then scan
    gemm_wi_kernel<<<gg, 256>>>(x, Wi0, bi0, ip, Sz * H, H);
    gru_scan_kernel<<<NBLK, NTHR, SMEM_BYTES>>>(ip, Wh0, bh0, y0, nullptr, 0);

    // layer 1: ip = y0 @ Wi1^T + bi1 (y0 is [s][b][h] -> rows contiguous), then scan
    gemm_wi_kernel<<<gg, 256>>>(y0, Wi1, bi1, ip, H, Bz * H);
    gru_scan_kernel<<<NBLK, NTHR, SMEM_BYTES>>>(ip, Wh1, bh1, out,
                                                out + (size_t)Bz * Sz * H, 1);

    (void)in_sizes; (void)n_in; (void)out_size;
}